// round 1
// baseline (speedup 1.0000x reference)
#include <cuda_runtime.h>
#include <cuda_bf16.h>

// Problem constants
#define N_ 16384
#define T_ 60
#define M_ 8
#define K_ 2
#define LOG_2PI 1.8378770664093453f

// Scratch (no device allocation allowed -> __device__ globals)
__device__ double g_num[T_];
__device__ double g_den[T_];
__device__ float  g_logZ[N_];   // logsumexp of pi logits per n

// ---------------------------------------------------------------------------
// Zero the per-timestep accumulators (runs every launch; graph-capturable)
// ---------------------------------------------------------------------------
__global__ void zero_kernel() {
    int i = threadIdx.x;
    if (i < T_) {
        g_num[i] = 0.0;
        g_den[i] = 0.0;
    }
}

// ---------------------------------------------------------------------------
// Precompute logZ[n] = logsumexp(pi[n, :]) once per n (instead of 60x/row)
// ---------------------------------------------------------------------------
__global__ void logz_kernel(const float* __restrict__ pi) {
    int n = blockIdx.x * blockDim.x + threadIdx.x;
    if (n >= N_) return;
    const float4* p4 = reinterpret_cast<const float4*>(pi + (size_t)n * M_);
    float4 a = p4[0];
    float4 b = p4[1];
    float mx = fmaxf(fmaxf(fmaxf(a.x, a.y), fmaxf(a.z, a.w)),
                     fmaxf(fmaxf(b.x, b.y), fmaxf(b.z, b.w)));
    float s = __expf(a.x - mx) + __expf(a.y - mx) + __expf(a.z - mx) + __expf(a.w - mx)
            + __expf(b.x - mx) + __expf(b.y - mx) + __expf(b.z - mx) + __expf(b.w - mx);
    g_logZ[n] = mx + __logf(s);
}

// ---------------------------------------------------------------------------
// Main fused kernel: one thread per (n, t)
//   Per component m (K=2 closed form, no cholesky / sqrt / solve):
//     det  = s00*s11 - s01*s10
//     maha = (s11*d0^2 - 2*s01*d0*d1 + s00*d1^2) / det
//     mvn_lp = -LOG_2PI - 0.5*maha - 0.5*log(det)
//   gmm_lp = lse_m(pi_m + mvn_lp_m) - logZ[n]
//   loss   = -gmm_lp;  accumulate loss*mask and mask per t.
// ---------------------------------------------------------------------------
__global__ __launch_bounds__(512) void nll_main_kernel(
    const float* __restrict__ mu,
    const float* __restrict__ sigma,
    const float* __restrict__ pi,
    const float* __restrict__ x,
    const float* __restrict__ mask)
{
    __shared__ float s_num[T_];
    __shared__ float s_den[T_];
    int tid = threadIdx.x;
    if (tid < T_) { s_num[tid] = 0.0f; s_den[tid] = 0.0f; }
    __syncthreads();

    int idx = blockIdx.x * blockDim.x + tid;      // idx = n*T + t
    if (idx < N_ * T_) {
        int n = idx / T_;
        int t = idx - n * T_;

        // x[n][t][:] : 2 floats, 8B aligned
        float2 xv = reinterpret_cast<const float2*>(x)[idx];
        float x0 = xv.x, x1 = xv.y;
        float mk = mask[idx];

        const float4* mu4 = reinterpret_cast<const float4*>(mu + (size_t)idx * (M_ * K_));
        const float4* sg4 = reinterpret_cast<const float4*>(sigma + (size_t)idx * (M_ * K_ * K_));
        const float*  pin = pi + (size_t)n * M_;

        float lp[M_];
        #pragma unroll
        for (int c = 0; c < M_ / 2; c++) {
            float4 mv = mu4[c];                  // components 2c (x,y) and 2c+1 (z,w)
            float4 sA = sg4[2 * c];              // [s00, s01, s10, s11] for comp 2c
            float4 sB = sg4[2 * c + 1];          // for comp 2c+1

            {
                float d0 = x0 - mv.x, d1 = x1 - mv.y;
                float det = fmaf(sA.x, sA.w, -sA.y * sA.z);
                float rdet = __frcp_rn(det);
                float quad = fmaf(d0 * d0, sA.w, fmaf(-2.0f * sA.y, d0 * d1, d1 * d1 * sA.x));
                lp[2 * c] = -LOG_2PI - 0.5f * quad * rdet - 0.5f * __logf(det);
            }
            {
                float d0 = x0 - mv.z, d1 = x1 - mv.w;
                float det = fmaf(sB.x, sB.w, -sB.y * sB.z);
                float rdet = __frcp_rn(det);
                float quad = fmaf(d0 * d0, sB.w, fmaf(-2.0f * sB.y, d0 * d1, d1 * d1 * sB.x));
                lp[2 * c + 1] = -LOG_2PI - 0.5f * quad * rdet - 0.5f * __logf(det);
            }
        }

        // add (unnormalized) pi logits; normalization via precomputed logZ[n]
        #pragma unroll
        for (int m = 0; m < M_; m++) lp[m] += __ldg(pin + m);

        float mx = lp[0];
        #pragma unroll
        for (int m = 1; m < M_; m++) mx = fmaxf(mx, lp[m]);
        float s = 0.0f;
        #pragma unroll
        for (int m = 0; m < M_; m++) s += __expf(lp[m] - mx);

        float gmm_lp = mx + __logf(s) - g_logZ[n];
        float loss = -gmm_lp;

        atomicAdd(&s_num[t], loss * mk);
        atomicAdd(&s_den[t], mk);
    }
    __syncthreads();

    if (tid < T_) {
        atomicAdd(&g_num[tid], (double)s_num[tid]);
        atomicAdd(&g_den[tid], (double)s_den[tid]);
    }
}

// ---------------------------------------------------------------------------
// Finalize: out = sum_t g_num[t] / g_den[t]
// ---------------------------------------------------------------------------
__global__ void finalize_kernel(float* __restrict__ out) {
    int tid = threadIdx.x;     // 64 threads
    double v = 0.0;
    if (tid < T_) v = g_num[tid] / g_den[tid];

    // warp reduce (2 warps of 32)
    #pragma unroll
    for (int off = 16; off > 0; off >>= 1)
        v += __shfl_down_sync(0xFFFFFFFFu, v, off);

    __shared__ double partial[2];
    if ((tid & 31) == 0) partial[tid >> 5] = v;
    __syncthreads();
    if (tid == 0) out[0] = (float)(partial[0] + partial[1]);
}

// ---------------------------------------------------------------------------
extern "C" void kernel_launch(void* const* d_in, const int* in_sizes, int n_in,
                              void* d_out, int out_size) {
    const float* mu    = (const float*)d_in[0];
    const float* sigma = (const float*)d_in[1];
    const float* pi    = (const float*)d_in[2];
    const float* x     = (const float*)d_in[3];
    const float* mask  = (const float*)d_in[4];
    float* out = (float*)d_out;

    zero_kernel<<<1, 64>>>();
    logz_kernel<<<(N_ + 255) / 256, 256>>>(pi);

    int total = N_ * T_;
    int threads = 512;
    int blocks = (total + threads - 1) / threads;   // 1920
    nll_main_kernel<<<blocks, threads>>>(mu, sigma, pi, x, mask);

    finalize_kernel<<<1, 64>>>(out);
}